// round 16
// baseline (speedup 1.0000x reference)
#include <cuda_runtime.h>
#include <cuda_bf16.h>
#include <math.h>
#include <stdint.h>

#define BB   16
#define QL   128
#define VLM  2048
#define HH   16
#define HKV  8
#define DD   128
#define HID  2048
#define GG   2
#define KVL  2176          // VLM + QL
#define NQKV 4096          // (H + 2*HKV) * D
#define KP   6144          // split K' = 3 * 2048 (A=[hi,hi,lo], B=[hi,lo,hi])

// ---------------- scratch (device globals; no allocation allowed) ----------------
__device__ float g_vn [BB * HKV * QL * DD];
__device__ float g_cos[KVL * 64];
__device__ float g_sin[KVL * 64];
__device__ __nv_bfloat16 g_h2[2048 * KP];                 // hidden split (A-flavor)
__device__ __nv_bfloat16 g_w1[4096 * KP];                 // wqkv split (B-flavor)
__device__ __nv_bfloat16 g_w2[2048 * KP];                 // wo split (B-flavor)
__device__ __nv_bfloat16 g_a2[2048 * KP];                 // attn-out split (A-flavor)
__device__ __nv_bfloat16 g_qs[BB * HH * QL * 256];        // Q split [bh][q][hi128|lo128], pre-scaled
__device__ __nv_bfloat16 g_ks[BB * HKV * KVL * 256];      // K split [bhk][p][hi128|lo128], roped
__device__ __nv_bfloat16 g_vt[BB * HKV * 2 * DD * KVL];   // V^T [bhk][hi/lo][d][kv]

// ---------------- helpers ----------------
__device__ __forceinline__ uint32_t smem_u32(const void* p) {
    uint32_t a;
    asm("{ .reg .u64 t; cvta.to.shared.u64 t, %1; cvt.u32.u64 %0, t; }" : "=r"(a) : "l"(p));
    return a;
}
__device__ __forceinline__ void cp_async16(uint32_t saddr, const void* g) {
    asm volatile("cp.async.cg.shared.global [%0], [%1], 16;" :: "r"(saddr), "l"(g));
}
#define CP_COMMIT() asm volatile("cp.async.commit_group;" ::: "memory")
#define CP_WAIT1()  asm volatile("cp.async.wait_group 1;" ::: "memory")
#define CP_WAIT0()  asm volatile("cp.async.wait_group 0;" ::: "memory")

#define LDMX4(r0, r1, r2, r3, addr) \
    asm volatile("ldmatrix.sync.aligned.m8n8.x4.shared.b16 {%0,%1,%2,%3}, [%4];" \
        : "=r"(r0), "=r"(r1), "=r"(r2), "=r"(r3) : "r"(addr))

#define MMA16816(d, a, b0_, b1_) \
    asm volatile("mma.sync.aligned.m16n8k16.row.col.f32.bf16.bf16.f32 " \
        "{%0,%1,%2,%3}, {%4,%5,%6,%7}, {%8,%9}, {%0,%1,%2,%3};" \
        : "+f"((d)[0]), "+f"((d)[1]), "+f"((d)[2]), "+f"((d)[3]) \
        : "r"((a)[0]), "r"((a)[1]), "r"((a)[2]), "r"((a)[3]), "r"(b0_), "r"(b1_))

__device__ __forceinline__ uint32_t swz(uint32_t x) { return x ^ ((x >> 3) & 0x70); }
__device__ __forceinline__ uint32_t pack_bf2(float x, float y) {
    __nv_bfloat162 t = __floats2bfloat162_rn(x, y);
    return *(uint32_t*)&t;
}
__device__ __forceinline__ uint4 pack8(const unsigned short* v) {
    return make_uint4((uint32_t)v[0] | ((uint32_t)v[1] << 16),
                      (uint32_t)v[2] | ((uint32_t)v[3] << 16),
                      (uint32_t)v[4] | ((uint32_t)v[5] << 16),
                      (uint32_t)v[6] | ((uint32_t)v[7] << 16));
}

// ---------------- RoPE tables ----------------
__global__ void rope_table_kernel() {
    int idx = blockIdx.x * blockDim.x + threadIdx.x;
    if (idx >= KVL * 64) return;
    int p = idx >> 6;
    int i = idx & 63;
    float inv = powf(10000.0f, -2.0f * (float)i / 128.0f);
    float ang = (float)p * inv;
    g_cos[idx] = cosf(ang);
    g_sin[idx] = sinf(ang);
}

// ---------------- fp32 -> bf16 3-way split (vectorized, 8 elems/thread) -----------
__global__ void conv_split_kernel(const float* __restrict__ src,
                                  __nv_bfloat16* __restrict__ dst,
                                  int total8, int bflavor) {
    int t = blockIdx.x * blockDim.x + threadIdx.x;
    if (t >= total8) return;
    int idx = t * 8;
    int r = idx >> 11;
    int k = idx & 2047;
    float4 x0 = *(const float4*)(src + idx);
    float4 x1 = *(const float4*)(src + idx + 4);
    float xs[8] = {x0.x, x0.y, x0.z, x0.w, x1.x, x1.y, x1.z, x1.w};
    unsigned short hi[8], lo[8];
#pragma unroll
    for (int i = 0; i < 8; i++) {
        __nv_bfloat16 h = __float2bfloat16(xs[i]);
        __nv_bfloat16 l = __float2bfloat16(xs[i] - __bfloat162float(h));
        hi[i] = *(unsigned short*)&h;
        lo[i] = *(unsigned short*)&l;
    }
    __nv_bfloat16* row = dst + (size_t)r * KP;
    uint4 hv = pack8(hi), lv = pack8(lo);
    *(uint4*)(row + k)        = hv;
    *(uint4*)(row + 2048 + k) = bflavor ? lv : hv;
    *(uint4*)(row + 4096 + k) = bflavor ? hv : lv;
}

// ---------------- mma.sync bf16 GEMM: 256x128 tile, 512 threads, 3 stages ---------
#define G_STAGE_BYTES 49152
#define GSMEM (3 * G_STAGE_BYTES)

__global__ __launch_bounds__(512, 1)
void gemm_mma_kernel(const __nv_bfloat16* __restrict__ A2,
                     const __nv_bfloat16* __restrict__ B2,
                     float* __restrict__ C, int Ncols,
                     int mode, const int* __restrict__ pos_ids) {
    extern __shared__ __align__(1024) char dsm[];
    uint32_t sbase = smem_u32(dsm);

    int tid = threadIdx.x;
    int lane = tid & 31;
    int wid = tid >> 5;
    int warp_m = wid & 3;
    int warp_n = wid >> 2;

    int row0 = blockIdx.y * 256;
    int col0 = blockIdx.x * 128;

    int r_ = tid >> 3;
    int ch = tid & 7;
    uint32_t so = swz((uint32_t)(r_ * 128 + ch * 16));
    const __nv_bfloat16* gA = A2 + (size_t)(row0 + r_) * KP + ch * 8;
    const __nv_bfloat16* gB = B2 + (size_t)(col0 + r_) * KP + ch * 8;

#define G_ISSUE(f_, buf_) do {                                           \
    uint32_t b_ = sbase + (uint32_t)(buf_) * G_STAGE_BYTES;              \
    int k_ = (f_) * 64;                                                  \
    _Pragma("unroll")                                                    \
    for (int i_ = 0; i_ < 4; i_++)                                       \
        cp_async16(b_ + so + i_ * 8192u, gA + k_ + (size_t)i_ * 64 * KP);\
    _Pragma("unroll")                                                    \
    for (int i_ = 0; i_ < 2; i_++)                                       \
        cp_async16(b_ + 32768u + so + i_ * 8192u,                        \
                   gB + k_ + (size_t)i_ * 64 * KP);                      \
} while (0)

    float c[4][4][4];
#pragma unroll
    for (int mt = 0; mt < 4; mt++)
#pragma unroll
        for (int nt = 0; nt < 4; nt++)
#pragma unroll
            for (int k = 0; k < 4; k++) c[mt][nt][k] = 0.0f;

    const int NS = KP / 64;
    G_ISSUE(0, 0); CP_COMMIT();
    G_ISSUE(1, 1); CP_COMMIT();

    int rowA = warp_m * 64 + (lane & 15);
    int rowB = warp_n * 32 + (lane & 15);
    int kb_half = ((lane >> 4) & 1) * 16;

    for (int s = 0; s < NS; s++) {
        CP_WAIT1();
        __syncthreads();
        if (s + 2 < NS) G_ISSUE(s + 2, (s + 2) % 3);
        CP_COMMIT();

        uint32_t sA = sbase + (uint32_t)(s % 3) * G_STAGE_BYTES;
        uint32_t sB = sA + 32768u;
#pragma unroll
        for (int ks = 0; ks < 4; ks++) {
            int kb = ks * 32 + kb_half;
            uint32_t a[4][4];
#pragma unroll
            for (int mt = 0; mt < 4; mt++) {
                uint32_t off = swz((uint32_t)((rowA + mt * 16) * 128 + kb));
                LDMX4(a[mt][0], a[mt][1], a[mt][2], a[mt][3], sA + off);
            }
            uint32_t b[2][4];
#pragma unroll
            for (int nt2 = 0; nt2 < 2; nt2++) {
                uint32_t off = swz((uint32_t)((rowB + nt2 * 16) * 128 + kb));
                LDMX4(b[nt2][0], b[nt2][1], b[nt2][2], b[nt2][3], sB + off);
            }
#pragma unroll
            for (int mt = 0; mt < 4; mt++)
#pragma unroll
                for (int nt = 0; nt < 4; nt++) {
                    int nt2 = nt >> 1, hb = nt & 1;
                    MMA16816(c[mt][nt], a[mt], b[nt2][hb], b[nt2][hb + 2]);
                }
        }
        __syncthreads();
    }

    if (mode == 0) {
#pragma unroll
        for (int mt = 0; mt < 4; mt++)
#pragma unroll
            for (int nt = 0; nt < 4; nt++) {
                int rg = row0 + warp_m * 64 + mt * 16 + (lane >> 2);
                int cg = col0 + warp_n * 32 + nt * 8 + (lane & 3) * 2;
                float* p0 = C + (size_t)rg * Ncols + cg;
                float* p1 = C + (size_t)(rg + 8) * Ncols + cg;
                *(float2*)p0 = make_float2(c[mt][nt][0], c[mt][nt][1]);
                *(float2*)p1 = make_float2(c[mt][nt][2], c[mt][nt][3]);
            }
        return;
    }

    // ---- fused QKV epilogue: two 128-row halves through smem ----
    float* sC = (float*)dsm;
    int bx = blockIdx.x;
    int hkv = bx >> 2;
    int slot = bx & 3;
    const float SCQ = 0.08838834764831845f;

#pragma unroll
    for (int hh = 0; hh < 2; hh++) {
        __syncthreads();
        if ((warp_m >> 1) == hh) {
#pragma unroll
            for (int mt = 0; mt < 4; mt++)
#pragma unroll
                for (int nt = 0; nt < 4; nt++) {
                    int rle = (warp_m & 1) * 64 + mt * 16 + (lane >> 2);
                    int ce = warp_n * 32 + nt * 8 + (lane & 3) * 2;
                    sC[rle * 132 + ce]           = c[mt][nt][0];
                    sC[rle * 132 + ce + 1]       = c[mt][nt][1];
                    sC[(rle + 8) * 132 + ce]     = c[mt][nt][2];
                    sC[(rle + 8) * 132 + ce + 1] = c[mt][nt][3];
                }
        }
        __syncthreads();

        for (int f = tid; f < 128 * 128; f += 512) {
            int rle = f >> 7;
            int di = f & 127;
            int rowg = row0 + hh * 128 + rle;
            int b = rowg >> 7, q = rowg & 127;
            float v = sC[rle * 132 + di];

            if (slot == 3) {
                g_vn[((b * HKV + hkv) * QL + q) * DD + di] = v;
                continue;
            }
            int pos = (slot == 2) ? (VLM + q) : (pos_ids[b * QL + q] + (KVL - QL));
            int i = di & 63;
            float co = g_cos[pos * 64 + i];
            float si = g_sin[pos * 64 + i];
            float partner = sC[rle * 132 + (di ^ 64)];
            float rot = (di < 64) ? -partner : partner;
            float outv = v * co + rot * si;

            if (slot == 2) {
                __nv_bfloat16 hi = __float2bfloat16(outv);
                __nv_bfloat16 lo = __float2bfloat16(outv - __bfloat162float(hi));
                size_t base = ((size_t)(b * HKV + hkv) * KVL + VLM + q) * 256 + di;
                g_ks[base] = hi;
                g_ks[base + 128] = lo;
            } else {
                float x = outv * SCQ;
                __nv_bfloat16 hi = __float2bfloat16(x);
                __nv_bfloat16 lo = __float2bfloat16(x - __bfloat162float(hi));
                int h = hkv * GG + slot;
                size_t base = ((size_t)(b * HH + h) * QL + q) * 256 + di;
                g_qs[base] = hi;
                g_qs[base + 128] = lo;
            }
        }
    }
}

// ---------------- prep VLM keys: RoPE + split (vectorized) --------
__global__ void prep_k_kernel(const float* __restrict__ vlm_k) {
    int idx = blockIdx.x * blockDim.x + threadIdx.x;
    int d0 = (idx & 15) * 8;
    int p  = (idx >> 4) & 2047;
    int bh = idx >> 15;
    const float* kp = vlm_k + ((size_t)bh * VLM + p) * DD;
    float4 x0 = *(const float4*)(kp + d0);
    float4 x1 = *(const float4*)(kp + d0 + 4);
    float4 y0 = *(const float4*)(kp + (d0 ^ 64));
    float4 y1 = *(const float4*)(kp + (d0 ^ 64) + 4);
    float xs[8] = {x0.x, x0.y, x0.z, x0.w, x1.x, x1.y, x1.z, x1.w};
    float ys[8] = {y0.x, y0.y, y0.z, y0.w, y1.x, y1.y, y1.z, y1.w};
    int i0 = d0 & 63;
    const float* cp = g_cos + p * 64 + i0;
    const float* sp = g_sin + p * 64 + i0;
    float sgn = (d0 < 64) ? -1.0f : 1.0f;
    unsigned short hi[8], lo[8];
#pragma unroll
    for (int j = 0; j < 8; j++) {
        float r = xs[j] * cp[j] + sgn * ys[j] * sp[j];
        __nv_bfloat16 h = __float2bfloat16(r);
        __nv_bfloat16 l = __float2bfloat16(r - __bfloat162float(h));
        hi[j] = *(unsigned short*)&h;
        lo[j] = *(unsigned short*)&l;
    }
    size_t base = ((size_t)bh * KVL + p) * 256 + d0;
    *(uint4*)(g_ks + base)       = pack8(hi);
    *(uint4*)(g_ks + base + 128) = pack8(lo);
}

// ---------------- prep V^T: transpose + split into g_vt ----------------
__global__ __launch_bounds__(256)
void prep_vt_kernel(const float* __restrict__ vlm_v) {
    __shared__ unsigned short sHi[128][72];
    __shared__ unsigned short sLo[128][72];
    int bh = blockIdx.x;
    int t  = blockIdx.y;
    int p0 = t * 64;
    const float* src = (t < 32)
        ? vlm_v + ((size_t)bh * VLM + p0) * DD
        : g_vn + ((size_t)bh * QL + (p0 - VLM)) * DD;
    int tid = threadIdx.x;
#pragma unroll
    for (int i = 0; i < 8; i++) {
        int f = tid + i * 256;
        int j = f >> 5;
        int d0 = (f & 31) * 4;
        float4 x = *(const float4*)(src + j * DD + d0);
        float vv[4] = {x.x, x.y, x.z, x.w};
#pragma unroll
        for (int e = 0; e < 4; e++) {
            __nv_bfloat16 hi = __float2bfloat16(vv[e]);
            __nv_bfloat16 lo = __float2bfloat16(vv[e] - __bfloat162float(hi));
            sHi[d0 + e][j] = *(unsigned short*)&hi;
            sLo[d0 + e][j] = *(unsigned short*)&lo;
        }
    }
    __syncthreads();
    int plane = tid >> 7;
    int d = tid & 127;
    unsigned short* row = plane ? sLo[d] : sHi[d];
    __nv_bfloat16* dst = g_vt + (((size_t)bh * 2 + plane) * DD + d) * KVL + p0;
#pragma unroll
    for (int k = 0; k < 8; k++) {
        *(uint4*)(dst + k * 8) = pack8(row + k * 8);
    }
}

// ---------------- tensor-core flash attention (3-term, Q in registers) -----------
// smem: 3 KV stages x 64KB = 192KB. Q staged through stage 0 then kept in regs.
#define A_STG    65536
#define A_SMEM   (3 * A_STG)
#define NTILES   (KVL / 64)

__global__ __launch_bounds__(256, 1)
void attn_mma_kernel() {
    extern __shared__ __align__(1024) char smraw[];
    uint32_t sb = smem_u32(smraw);

    int bh = blockIdx.x;
    int b = bh >> 4, h = bh & 15;
    int bhk = (b << 3) | (h >> 1);
    int tid = threadIdx.x;
    int lane = tid & 31;
    int wid = tid >> 5;
    int r0 = wid * 16;

    uint32_t qrow = (uint32_t)((r0 + (lane & 15)) * 128 + ((lane >> 4) & 1) * 16);
    uint32_t krow = (uint32_t)((lane & 15) * 128 + ((lane >> 4) & 1) * 16);

    // ---- stage Q through buffer 0, load fragments to registers ----
    uint32_t qh[8][4], ql[8][4];
    {
        const __nv_bfloat16* gq = g_qs + (size_t)bh * QL * 256;
#pragma unroll
        for (int i = 0; i < 16; i++) {
            int u = tid + i * 256;
            int row = u >> 5, rem = u & 31;
            int plane = rem >> 3, ch = rem & 7;
            cp_async16(sb + plane * 16384 + swz(row * 128 + ch * 16),
                       gq + row * 256 + plane * 64 + ch * 8);
        }
        CP_COMMIT();
        CP_WAIT0();
        __syncthreads();
#pragma unroll
        for (int ks = 0; ks < 8; ks++) {
            uint32_t co = (uint32_t)((ks & 3) * 32);
            uint32_t pq = (uint32_t)((ks >> 2) * 16384);
            uint32_t qoff = swz(qrow + co);
            LDMX4(qh[ks][0], qh[ks][1], qh[ks][2], qh[ks][3], sb + pq + qoff);
            LDMX4(ql[ks][0], ql[ks][1], ql[ks][2], ql[ks][3], sb + 32768u + pq + qoff);
        }
        __syncthreads();   // all warps done reading buf0 before KV overwrites it
    }

    // ---- KV tile load slots ----
    const __nv_bfloat16* gK[8]; uint32_t sKo[8];
    const __nv_bfloat16* gV[8]; uint32_t sVo[8];
#pragma unroll
    for (int i = 0; i < 8; i++) {
        int u = tid + i * 256;
        int row = u >> 5, rem = u & 31;
        int plane = rem >> 3, ch = rem & 7;
        gK[i] = g_ks + ((size_t)bhk * KVL + row) * 256 + plane * 64 + ch * 8;
        sKo[i] = plane * 8192 + swz(row * 128 + ch * 16);
    }
#pragma unroll
    for (int i = 0; i < 8; i++) {
        int u = tid + i * 256;
        int plane = u >> 10, d = (u >> 3) & 127, ch = u & 7;
        gV[i] = g_vt + (((size_t)bhk * 2 + plane) * DD + d) * KVL + ch * 8;
        sVo[i] = 32768 + plane * 16384 + swz(d * 128 + ch * 16);
    }

    auto issue_kv = [&](int tt, int buf) {
        uint32_t base_ = sb + (uint32_t)buf * A_STG;
#pragma unroll
        for (int i = 0; i < 8; i++) cp_async16(base_ + sKo[i], gK[i] + (size_t)tt * 64 * 256);
#pragma unroll
        for (int i = 0; i < 8; i++) cp_async16(base_ + sVo[i], gV[i] + tt * 64);
    };

    issue_kv(0, 0); CP_COMMIT();
    issue_kv(1, 1); CP_COMMIT();

    float o[16][4];
#pragma unroll
    for (int dt = 0; dt < 16; dt++)
#pragma unroll
        for (int k = 0; k < 4; k++) o[dt][k] = 0.0f;
    float m0 = -1e30f, m1 = -1e30f, l0 = 0.0f, l1 = 0.0f;

    for (int t = 0; t < NTILES; t++) {
        CP_WAIT1();
        __syncthreads();
        // prefetch t+2 into the stage tile t-1 vacated (safe after the sync)
        if (t + 2 < NTILES) issue_kv(t + 2, (t + 2) % 3);
        CP_COMMIT();

        uint32_t sK_ = sb + (uint32_t)(t % 3) * A_STG;
        uint32_t sV_ = sK_;

        // ---- S = Q K^T, 3 split terms, Q from registers ----
        float sc[8][4];
#pragma unroll
        for (int nt = 0; nt < 8; nt++)
#pragma unroll
            for (int k = 0; k < 4; k++) sc[nt][k] = 0.0f;

#pragma unroll
        for (int ks = 0; ks < 8; ks++) {
            uint32_t co = (uint32_t)((ks & 3) * 32);
            uint32_t pk = (uint32_t)((ks >> 2) * 8192);
            uint32_t bhx[4][4], blx[4][4];
#pragma unroll
            for (int g = 0; g < 4; g++) {
                uint32_t koff = swz(krow + g * 2048 + co);
                LDMX4(bhx[g][0], bhx[g][1], bhx[g][2], bhx[g][3], sK_ + pk + koff);
                LDMX4(blx[g][0], blx[g][1], blx[g][2], blx[g][3], sK_ + 16384u + pk + koff);
            }
#pragma unroll
            for (int nt = 0; nt < 8; nt++) {
                int g = nt >> 1, hb = nt & 1;
                MMA16816(sc[nt], qh[ks], bhx[g][hb], bhx[g][hb + 2]);
                MMA16816(sc[nt], qh[ks], blx[g][hb], blx[g][hb + 2]);
                MMA16816(sc[nt], ql[ks], bhx[g][hb], bhx[g][hb + 2]);
            }
        }

        // ---- mask (suffix tiles only) ----
        if (t >= 32) {
            int rg0 = r0 + (lane >> 2);
            int cb = t * 64 + (lane & 3) * 2;
#pragma unroll
            for (int nt = 0; nt < 8; nt++) {
                int c0 = cb + nt * 8;
                if (c0     > VLM + rg0)     sc[nt][0] = -1e30f;
                if (c0 + 1 > VLM + rg0)     sc[nt][1] = -1e30f;
                if (c0     > VLM + rg0 + 8) sc[nt][2] = -1e30f;
                if (c0 + 1 > VLM + rg0 + 8) sc[nt][3] = -1e30f;
            }
        }

        // ---- online softmax ----
        float rm0 = -1e30f, rm1 = -1e30f;
#pragma unroll
        for (int nt = 0; nt < 8; nt++) {
            rm0 = fmaxf(rm0, fmaxf(sc[nt][0], sc[nt][1]));
            rm1 = fmaxf(rm1, fmaxf(sc[nt][2], sc[nt][3]));
        }
        rm0 = fmaxf(rm0, __shfl_xor_sync(0xffffffffu, rm0, 1));
        rm0 = fmaxf(rm0, __shfl_xor_sync(0xffffffffu, rm0, 2));
        rm1 = fmaxf(rm1, __shfl_xor_sync(0xffffffffu, rm1, 1));
        rm1 = fmaxf(rm1, __shfl_xor_sync(0xffffffffu, rm1, 2));
        float mn0 = fmaxf(m0, rm0), mn1 = fmaxf(m1, rm1);
        float al0 = __expf(m0 - mn0), al1 = __expf(m1 - mn1);
        m0 = mn0; m1 = mn1;

        float rs0 = 0.0f, rs1 = 0.0f;
        uint32_t phi[4][4], plo[4][4];
#pragma unroll
        for (int nt = 0; nt < 8; nt++) {
            float p0f = __expf(sc[nt][0] - mn0);
            float p1f = __expf(sc[nt][1] - mn0);
            float p2f = __expf(sc[nt][2] - mn1);
            float p3f = __expf(sc[nt][3] - mn1);
            rs0 += p0f + p1f;
            rs1 += p2f + p3f;
            float h0 = __bfloat162float(__float2bfloat16(p0f));
            float h1 = __bfloat162float(__float2bfloat16(p1f));
            float h2 = __bfloat162float(__float2bfloat16(p2f));
            float h3 = __bfloat162float(__float2bfloat16(p3f));
            int kk = nt >> 1;
            int off = (nt & 1) * 2;
            phi[kk][off]     = pack_bf2(h0, h1);
            phi[kk][off + 1] = pack_bf2(h2, h3);
            plo[kk][off]     = pack_bf2(p0f - h0, p1f - h1);
            plo[kk][off + 1] = pack_bf2(p2f - h2, p3f - h3);
        }
        rs0 += __shfl_xor_sync(0xffffffffu, rs0, 1);
        rs0 += __shfl_xor_sync(0xffffffffu, rs0, 2);
        rs1 += __shfl_xor_sync(0xffffffffu, rs1, 1);
        rs1 += __shfl_xor_sync(0xffffffffu, rs1, 2);
        l0 = l0 * al0 + rs0;
        l1 = l1 * al1 + rs1;
#pragma unroll
        for (int dt = 0; dt < 16; dt++) {
            o[dt][0] *= al0; o[dt][1] *= al0;
            o[dt][2] *= al1; o[dt][3] *= al1;
        }

        // ---- O += P V  (3 split terms) ----
#pragma unroll
        for (int kk = 0; kk < 4; kk++) {
            uint32_t co = (uint32_t)(kk * 32);
#pragma unroll
            for (int g = 0; g < 8; g++) {
                uint32_t bhx[4], blx[4];
                uint32_t roff = swz(krow + g * 2048 + co);
                LDMX4(bhx[0], bhx[1], bhx[2], bhx[3], sV_ + 32768 + roff);
                LDMX4(blx[0], blx[1], blx[2], blx[3], sV_ + 49152 + roff);
                MMA16816(o[2*g],   phi[kk], bhx[0], bhx[2]);
                MMA16816(o[2*g],   phi[kk], blx[0], blx[2]);
                MMA16816(o[2*g],   plo[kk], bhx[0], bhx[2]);
                MMA16816(o[2*g+1], phi[kk], bhx[1], bhx[3]);
                MMA16816(o[2*g+1], phi[kk], blx[1], blx[3]);
                MMA16816(o[2*g+1], plo[kk], bhx[1], bhx[3]);
            }
        }
    }

    // ---- epilogue: write split a2 (A-flavor [hi,hi,lo]) directly ----
    float i0 = 1.0f / l0, i1 = 1.0f / l1;
    int q0 = r0 + (lane >> 2);
    int cb = (lane & 3) * 2;
#pragma unroll
    for (int dt = 0; dt < 16; dt++) {
        int k = h * DD + cb + dt * 8;
        float v0 = o[dt][0] * i0, v1 = o[dt][1] * i0;
        float v2 = o[dt][2] * i1, v3 = o[dt][3] * i1;
        __nv_bfloat16 h0 = __float2bfloat16(v0), h1 = __float2bfloat16(v1);
        __nv_bfloat16 h2 = __float2bfloat16(v2), h3 = __float2bfloat16(v3);
        uint32_t hp0 = pack_bf2(__bfloat162float(h0), __bfloat162float(h1));
        uint32_t hp1 = pack_bf2(__bfloat162float(h2), __bfloat162float(h3));
        uint32_t lp0 = pack_bf2(v0 - __bfloat162float(h0), v1 - __bfloat162float(h1));
        uint32_t lp1 = pack_bf2(v2 - __bfloat162float(h2), v3 - __bfloat162float(h3));
        __nv_bfloat16* r0p = g_a2 + ((size_t)b * QL + q0) * KP;
        __nv_bfloat16* r1p = g_a2 + ((size_t)b * QL + q0 + 8) * KP;
        *(uint32_t*)(r0p + k)        = hp0;
        *(uint32_t*)(r0p + 2048 + k) = hp0;
        *(uint32_t*)(r0p + 4096 + k) = lp0;
        *(uint32_t*)(r1p + k)        = hp1;
        *(uint32_t*)(r1p + 2048 + k) = hp1;
        *(uint32_t*)(r1p + 4096 + k) = lp1;
    }
}

// ---------------- launch ----------------
extern "C" void kernel_launch(void* const* d_in, const int* in_sizes, int n_in,
                              void* d_out, int out_size) {
    const float* hidden = (const float*)d_in[0];
    const float* vlm_k  = (const float*)d_in[1];
    const float* vlm_v  = (const float*)d_in[2];
    const int*   pos    = (const int*)d_in[3];
    // d_in[4] attention_mask: reproduced analytically (prefix-visible + causal suffix)
    const float* wqkv   = (const float*)d_in[5];
    const float* wo     = (const float*)d_in[6];
    float* out = (float*)d_out;

    __nv_bfloat16 *h2_p, *w1_p, *w2_p, *a2_p;
    cudaGetSymbolAddress((void**)&h2_p, g_h2);
    cudaGetSymbolAddress((void**)&w1_p, g_w1);
    cudaGetSymbolAddress((void**)&w2_p, g_w2);
    cudaGetSymbolAddress((void**)&a2_p, g_a2);

    rope_table_kernel<<<(KVL * 64 + 255) / 256, 256>>>();

    prep_k_kernel<<<(128 * 2048 * 16) / 256, 256>>>(vlm_k);

    conv_split_kernel<<<(2048 * 2048 / 8) / 256, 256>>>(hidden, h2_p, 2048 * 2048 / 8, 0);
    conv_split_kernel<<<(4096 * 2048 / 8) / 256, 256>>>(wqkv,   w1_p, 4096 * 2048 / 8, 1);
    conv_split_kernel<<<(2048 * 2048 / 8) / 256, 256>>>(wo,     w2_p, 2048 * 2048 / 8, 1);

    cudaFuncSetAttribute(gemm_mma_kernel, cudaFuncAttributeMaxDynamicSharedMemorySize, GSMEM);

    // QKV projection + fused RoPE/split epilogue (mode 1): 256x128 tiles
    gemm_mma_kernel<<<dim3(NQKV / 128, (BB * QL) / 256), 512, GSMEM>>>(
        h2_p, w1_p, nullptr, NQKV, 1, pos);

    prep_vt_kernel<<<dim3(128, NTILES), 256>>>(vlm_v);

    cudaFuncSetAttribute(attn_mma_kernel, cudaFuncAttributeMaxDynamicSharedMemorySize, A_SMEM);
    attn_mma_kernel<<<BB * HH, 256, A_SMEM>>>();

    // output projection (mode 0, plain store to d_out): 256x128 tiles
    gemm_mma_kernel<<<dim3(HID / 128, (BB * QL) / 256), 512, GSMEM>>>(
        a2_p, w2_p, out, HID, 0, nullptr);
}

// round 17
// speedup vs baseline: 1.5661x; 1.5661x over previous
#include <cuda_runtime.h>
#include <cuda_bf16.h>
#include <math.h>
#include <stdint.h>

#define BB   16
#define QL   128
#define VLM  2048
#define HH   16
#define HKV  8
#define DD   128
#define HID  2048
#define GG   2
#define KVL  2176          // VLM + QL
#define NQKV 4096          // (H + 2*HKV) * D
#define KP   6144          // split K' = 3 * 2048 (A=[hi,hi,lo], B=[hi,lo,hi])

// ---------------- scratch (device globals; no allocation allowed) ----------------
__device__ float g_vn [BB * HKV * QL * DD];
__device__ float g_cos[KVL * 64];
__device__ float g_sin[KVL * 64];
__device__ __nv_bfloat16 g_h2[2048 * KP];                 // hidden split (A-flavor)
__device__ __nv_bfloat16 g_w1[4096 * KP];                 // wqkv split (B-flavor)
__device__ __nv_bfloat16 g_w2[2048 * KP];                 // wo split (B-flavor)
__device__ __nv_bfloat16 g_a2[2048 * KP];                 // attn-out split (A-flavor)
__device__ __nv_bfloat16 g_qs[BB * HH * QL * 256];        // Q split [bh][q][hi128|lo128], pre-scaled
__device__ __nv_bfloat16 g_ks[BB * HKV * KVL * 256];      // K split [bhk][p][hi128|lo128], roped
__device__ __nv_bfloat16 g_vt[BB * HKV * 2 * DD * KVL];   // V^T [bhk][hi/lo][d][kv]

// ---------------- helpers ----------------
__device__ __forceinline__ uint32_t smem_u32(const void* p) {
    uint32_t a;
    asm("{ .reg .u64 t; cvta.to.shared.u64 t, %1; cvt.u32.u64 %0, t; }" : "=r"(a) : "l"(p));
    return a;
}
__device__ __forceinline__ void cp_async16(uint32_t saddr, const void* g) {
    asm volatile("cp.async.cg.shared.global [%0], [%1], 16;" :: "r"(saddr), "l"(g));
}
#define CP_COMMIT() asm volatile("cp.async.commit_group;" ::: "memory")
#define CP_WAIT1()  asm volatile("cp.async.wait_group 1;" ::: "memory")

#define LDMX4(r0, r1, r2, r3, addr) \
    asm volatile("ldmatrix.sync.aligned.m8n8.x4.shared.b16 {%0,%1,%2,%3}, [%4];" \
        : "=r"(r0), "=r"(r1), "=r"(r2), "=r"(r3) : "r"(addr))

#define MMA16816(d, a, b0_, b1_) \
    asm volatile("mma.sync.aligned.m16n8k16.row.col.f32.bf16.bf16.f32 " \
        "{%0,%1,%2,%3}, {%4,%5,%6,%7}, {%8,%9}, {%0,%1,%2,%3};" \
        : "+f"((d)[0]), "+f"((d)[1]), "+f"((d)[2]), "+f"((d)[3]) \
        : "r"((a)[0]), "r"((a)[1]), "r"((a)[2]), "r"((a)[3]), "r"(b0_), "r"(b1_))

__device__ __forceinline__ uint32_t swz(uint32_t x) { return x ^ ((x >> 3) & 0x70); }
__device__ __forceinline__ uint32_t pack_bf2(float x, float y) {
    __nv_bfloat162 t = __floats2bfloat162_rn(x, y);
    return *(uint32_t*)&t;
}
__device__ __forceinline__ uint4 pack8(const unsigned short* v) {
    return make_uint4((uint32_t)v[0] | ((uint32_t)v[1] << 16),
                      (uint32_t)v[2] | ((uint32_t)v[3] << 16),
                      (uint32_t)v[4] | ((uint32_t)v[5] << 16),
                      (uint32_t)v[6] | ((uint32_t)v[7] << 16));
}

// ---------------- RoPE tables ----------------
__global__ void rope_table_kernel() {
    int idx = blockIdx.x * blockDim.x + threadIdx.x;
    if (idx >= KVL * 64) return;
    int p = idx >> 6;
    int i = idx & 63;
    float inv = powf(10000.0f, -2.0f * (float)i / 128.0f);
    float ang = (float)p * inv;
    g_cos[idx] = cosf(ang);
    g_sin[idx] = sinf(ang);
}

// ---------------- fp32 -> bf16 3-way split (vectorized, 8 elems/thread) -----------
// A-flavor (0): [hi, hi, lo]; B-flavor (1): [hi, lo, hi]
__global__ void conv_split_kernel(const float* __restrict__ src,
                                  __nv_bfloat16* __restrict__ dst,
                                  int total8, int bflavor) {
    int t = blockIdx.x * blockDim.x + threadIdx.x;
    if (t >= total8) return;
    int idx = t * 8;
    int r = idx >> 11;
    int k = idx & 2047;
    float4 x0 = *(const float4*)(src + idx);
    float4 x1 = *(const float4*)(src + idx + 4);
    float xs[8] = {x0.x, x0.y, x0.z, x0.w, x1.x, x1.y, x1.z, x1.w};
    unsigned short hi[8], lo[8];
#pragma unroll
    for (int i = 0; i < 8; i++) {
        __nv_bfloat16 h = __float2bfloat16(xs[i]);
        __nv_bfloat16 l = __float2bfloat16(xs[i] - __bfloat162float(h));
        hi[i] = *(unsigned short*)&h;
        lo[i] = *(unsigned short*)&l;
    }
    __nv_bfloat16* row = dst + (size_t)r * KP;
    uint4 hv = pack8(hi), lv = pack8(lo);
    *(uint4*)(row + k)        = hv;
    *(uint4*)(row + 2048 + k) = bflavor ? lv : hv;
    *(uint4*)(row + 4096 + k) = bflavor ? hv : lv;
}

// ---------------- mma.sync bf16 GEMM: 256x128 tile, 512 threads, 3 stages ---------
// mode 0: plain C store.  mode 1: fused QKV epilogue (RoPE + split; no C store).
#define G_STAGE_BYTES 49152          // A 256x64 bf16 (32KB) + B 128x64 bf16 (16KB)
#define GSMEM (3 * G_STAGE_BYTES)    // 147456

__global__ __launch_bounds__(512, 1)
void gemm_mma_kernel(const __nv_bfloat16* __restrict__ A2,
                     const __nv_bfloat16* __restrict__ B2,
                     float* __restrict__ C, int Ncols,
                     int mode, const int* __restrict__ pos_ids) {
    extern __shared__ __align__(1024) char dsm[];
    uint32_t sbase = smem_u32(dsm);

    int tid = threadIdx.x;
    int lane = tid & 31;
    int wid = tid >> 5;
    int warp_m = wid & 3;            // 0..3  (64 rows each)
    int warp_n = wid >> 2;           // 0..3  (32 cols each)

    int row0 = blockIdx.y * 256;
    int col0 = blockIdx.x * 128;

    // loads: 6 x 16B per thread per stage (A: 4, B: 2)
    int r_ = tid >> 3;               // 0..63
    int ch = tid & 7;
    uint32_t so = swz((uint32_t)(r_ * 128 + ch * 16));
    const __nv_bfloat16* gA = A2 + (size_t)(row0 + r_) * KP + ch * 8;
    const __nv_bfloat16* gB = B2 + (size_t)(col0 + r_) * KP + ch * 8;

#define G_ISSUE(f_, buf_) do {                                           \
    uint32_t b_ = sbase + (uint32_t)(buf_) * G_STAGE_BYTES;              \
    int k_ = (f_) * 64;                                                  \
    _Pragma("unroll")                                                    \
    for (int i_ = 0; i_ < 4; i_++)                                       \
        cp_async16(b_ + so + i_ * 8192u, gA + k_ + (size_t)i_ * 64 * KP);\
    _Pragma("unroll")                                                    \
    for (int i_ = 0; i_ < 2; i_++)                                       \
        cp_async16(b_ + 32768u + so + i_ * 8192u,                        \
                   gB + k_ + (size_t)i_ * 64 * KP);                      \
} while (0)

    float c[4][4][4];
#pragma unroll
    for (int mt = 0; mt < 4; mt++)
#pragma unroll
        for (int nt = 0; nt < 4; nt++)
#pragma unroll
            for (int k = 0; k < 4; k++) c[mt][nt][k] = 0.0f;

    const int NS = KP / 64;          // 96
    G_ISSUE(0, 0); CP_COMMIT();
    G_ISSUE(1, 1); CP_COMMIT();

    int rowA = warp_m * 64 + (lane & 15);
    int rowB = warp_n * 32 + (lane & 15);
    int kb_half = ((lane >> 4) & 1) * 16;

    for (int s = 0; s < NS; s++) {
        CP_WAIT1();
        __syncthreads();
        if (s + 2 < NS) G_ISSUE(s + 2, (s + 2) % 3);
        CP_COMMIT();

        uint32_t sA = sbase + (uint32_t)(s % 3) * G_STAGE_BYTES;
        uint32_t sB = sA + 32768u;
#pragma unroll
        for (int ks = 0; ks < 4; ks++) {
            int kb = ks * 32 + kb_half;
            uint32_t a[4][4];
#pragma unroll
            for (int mt = 0; mt < 4; mt++) {
                uint32_t off = swz((uint32_t)((rowA + mt * 16) * 128 + kb));
                LDMX4(a[mt][0], a[mt][1], a[mt][2], a[mt][3], sA + off);
            }
            uint32_t b[2][4];
#pragma unroll
            for (int nt2 = 0; nt2 < 2; nt2++) {
                uint32_t off = swz((uint32_t)((rowB + nt2 * 16) * 128 + kb));
                LDMX4(b[nt2][0], b[nt2][1], b[nt2][2], b[nt2][3], sB + off);
            }
#pragma unroll
            for (int mt = 0; mt < 4; mt++)
#pragma unroll
                for (int nt = 0; nt < 4; nt++) {
                    int nt2 = nt >> 1, hb = nt & 1;
                    MMA16816(c[mt][nt], a[mt], b[nt2][hb], b[nt2][hb + 2]);
                }
        }
        __syncthreads();
    }

    if (mode == 0) {
#pragma unroll
        for (int mt = 0; mt < 4; mt++)
#pragma unroll
            for (int nt = 0; nt < 4; nt++) {
                int rg = row0 + warp_m * 64 + mt * 16 + (lane >> 2);
                int cg = col0 + warp_n * 32 + nt * 8 + (lane & 3) * 2;
                float* p0 = C + (size_t)rg * Ncols + cg;
                float* p1 = C + (size_t)(rg + 8) * Ncols + cg;
                *(float2*)p0 = make_float2(c[mt][nt][0], c[mt][nt][1]);
                *(float2*)p1 = make_float2(c[mt][nt][2], c[mt][nt][3]);
            }
        return;
    }

    // ---- fused QKV epilogue: two 128-row halves through smem ----
    float* sC = (float*)dsm;         // [128][132]
    int bx = blockIdx.x;             // hkv = bx>>2, slot = bx&3
    int hkv = bx >> 2;
    int slot = bx & 3;
    const float SCQ = 0.08838834764831845f;

#pragma unroll
    for (int hh = 0; hh < 2; hh++) {
        __syncthreads();
        if ((warp_m >> 1) == hh) {
#pragma unroll
            for (int mt = 0; mt < 4; mt++)
#pragma unroll
                for (int nt = 0; nt < 4; nt++) {
                    int rle = (warp_m & 1) * 64 + mt * 16 + (lane >> 2);
                    int ce = warp_n * 32 + nt * 8 + (lane & 3) * 2;
                    sC[rle * 132 + ce]           = c[mt][nt][0];
                    sC[rle * 132 + ce + 1]       = c[mt][nt][1];
                    sC[(rle + 8) * 132 + ce]     = c[mt][nt][2];
                    sC[(rle + 8) * 132 + ce + 1] = c[mt][nt][3];
                }
        }
        __syncthreads();

        for (int f = tid; f < 128 * 128; f += 512) {
            int rle = f >> 7;
            int di = f & 127;
            int rowg = row0 + hh * 128 + rle;
            int b = rowg >> 7, q = rowg & 127;
            float v = sC[rle * 132 + di];

            if (slot == 3) {
                g_vn[((b * HKV + hkv) * QL + q) * DD + di] = v;
                continue;
            }
            int pos = (slot == 2) ? (VLM + q) : (pos_ids[b * QL + q] + (KVL - QL));
            int i = di & 63;
            float co = g_cos[pos * 64 + i];
            float si = g_sin[pos * 64 + i];
            float partner = sC[rle * 132 + (di ^ 64)];
            float rot = (di < 64) ? -partner : partner;
            float outv = v * co + rot * si;

            if (slot == 2) {
                __nv_bfloat16 hi = __float2bfloat16(outv);
                __nv_bfloat16 lo = __float2bfloat16(outv - __bfloat162float(hi));
                size_t base = ((size_t)(b * HKV + hkv) * KVL + VLM + q) * 256 + di;
                g_ks[base] = hi;
                g_ks[base + 128] = lo;
            } else {
                float x = outv * SCQ;
                __nv_bfloat16 hi = __float2bfloat16(x);
                __nv_bfloat16 lo = __float2bfloat16(x - __bfloat162float(hi));
                int h = hkv * GG + slot;
                size_t base = ((size_t)(b * HH + h) * QL + q) * 256 + di;
                g_qs[base] = hi;
                g_qs[base + 128] = lo;
            }
        }
    }
}

// ---------------- prep VLM keys: RoPE + split (vectorized) --------
__global__ void prep_k_kernel(const float* __restrict__ vlm_k) {
    int idx = blockIdx.x * blockDim.x + threadIdx.x;   // 128 * 2048 * 16
    int d0 = (idx & 15) * 8;
    int p  = (idx >> 4) & 2047;
    int bh = idx >> 15;
    const float* kp = vlm_k + ((size_t)bh * VLM + p) * DD;
    float4 x0 = *(const float4*)(kp + d0);
    float4 x1 = *(const float4*)(kp + d0 + 4);
    float4 y0 = *(const float4*)(kp + (d0 ^ 64));
    float4 y1 = *(const float4*)(kp + (d0 ^ 64) + 4);
    float xs[8] = {x0.x, x0.y, x0.z, x0.w, x1.x, x1.y, x1.z, x1.w};
    float ys[8] = {y0.x, y0.y, y0.z, y0.w, y1.x, y1.y, y1.z, y1.w};
    int i0 = d0 & 63;
    const float* cp = g_cos + p * 64 + i0;
    const float* sp = g_sin + p * 64 + i0;
    float sgn = (d0 < 64) ? -1.0f : 1.0f;
    unsigned short hi[8], lo[8];
#pragma unroll
    for (int j = 0; j < 8; j++) {
        float r = xs[j] * cp[j] + sgn * ys[j] * sp[j];
        __nv_bfloat16 h = __float2bfloat16(r);
        __nv_bfloat16 l = __float2bfloat16(r - __bfloat162float(h));
        hi[j] = *(unsigned short*)&h;
        lo[j] = *(unsigned short*)&l;
    }
    size_t base = ((size_t)bh * KVL + p) * 256 + d0;
    *(uint4*)(g_ks + base)       = pack8(hi);
    *(uint4*)(g_ks + base + 128) = pack8(lo);
}

// ---------------- prep V^T: transpose + split into g_vt ----------------
__global__ __launch_bounds__(256)
void prep_vt_kernel(const float* __restrict__ vlm_v) {
    __shared__ unsigned short sHi[128][72];
    __shared__ unsigned short sLo[128][72];
    int bh = blockIdx.x;
    int t  = blockIdx.y;
    int p0 = t * 64;
    const float* src = (t < 32)
        ? vlm_v + ((size_t)bh * VLM + p0) * DD
        : g_vn + ((size_t)bh * QL + (p0 - VLM)) * DD;
    int tid = threadIdx.x;
#pragma unroll
    for (int i = 0; i < 8; i++) {
        int f = tid + i * 256;
        int j = f >> 5;
        int d0 = (f & 31) * 4;
        float4 x = *(const float4*)(src + j * DD + d0);
        float vv[4] = {x.x, x.y, x.z, x.w};
#pragma unroll
        for (int e = 0; e < 4; e++) {
            __nv_bfloat16 hi = __float2bfloat16(vv[e]);
            __nv_bfloat16 lo = __float2bfloat16(vv[e] - __bfloat162float(hi));
            sHi[d0 + e][j] = *(unsigned short*)&hi;
            sLo[d0 + e][j] = *(unsigned short*)&lo;
        }
    }
    __syncthreads();
    int plane = tid >> 7;
    int d = tid & 127;
    unsigned short* row = plane ? sLo[d] : sHi[d];
    __nv_bfloat16* dst = g_vt + (((size_t)bh * 2 + plane) * DD + d) * KVL + p0;
#pragma unroll
    for (int k = 0; k < 8; k++) {
        *(uint4*)(dst + k * 8) = pack8(row + k * 8);
    }
}

// ---------------- tensor-core flash attention (3-term, R14-proven) ----------------
#define A_QBYTES 65536
#define A_STG    65536
#define A_SMEM   (A_QBYTES + 2 * A_STG)
#define NTILES   (KVL / 64)

__global__ __launch_bounds__(256, 1)
void attn_mma_kernel() {
    extern __shared__ __align__(1024) char smraw[];
    uint32_t sb = smem_u32(smraw);

    int bh = blockIdx.x;
    int b = bh >> 4, h = bh & 15;
    int bhk = (b << 3) | (h >> 1);
    int tid = threadIdx.x;
    int lane = tid & 31;
    int wid = tid >> 5;
    int r0 = wid * 16;

    // ---- one-time Q load (4 planes of [128][64]) ----
    {
        const __nv_bfloat16* gq = g_qs + (size_t)bh * QL * 256;
#pragma unroll
        for (int i = 0; i < 16; i++) {
            int u = tid + i * 256;
            int row = u >> 5, rem = u & 31;
            int plane = rem >> 3, ch = rem & 7;
            cp_async16(sb + plane * 16384 + swz(row * 128 + ch * 16),
                       gq + row * 256 + plane * 64 + ch * 8);
        }
        CP_COMMIT();
    }

    // ---- KV tile load slots ----
    const __nv_bfloat16* gK[8]; uint32_t sKo[8];
    const __nv_bfloat16* gV[8]; uint32_t sVo[8];
#pragma unroll
    for (int i = 0; i < 8; i++) {
        int u = tid + i * 256;
        int row = u >> 5, rem = u & 31;
        int plane = rem >> 3, ch = rem & 7;
        gK[i] = g_ks + ((size_t)bhk * KVL + row) * 256 + plane * 64 + ch * 8;
        sKo[i] = plane * 8192 + swz(row * 128 + ch * 16);
    }
#pragma unroll
    for (int i = 0; i < 8; i++) {
        int u = tid + i * 256;
        int plane = u >> 10, d = (u >> 3) & 127, ch = u & 7;
        gV[i] = g_vt + (((size_t)bhk * 2 + plane) * DD + d) * KVL + ch * 8;
        sVo[i] = 32768 + plane * 16384 + swz(d * 128 + ch * 16);
    }

    auto issue_kv = [&](int tt, int buf) {
        uint32_t base_ = sb + A_QBYTES + (uint32_t)buf * A_STG;
#pragma unroll
        for (int i = 0; i < 8; i++) cp_async16(base_ + sKo[i], gK[i] + (size_t)tt * 64 * 256);
#pragma unroll
        for (int i = 0; i < 8; i++) cp_async16(base_ + sVo[i], gV[i] + tt * 64);
    };

    issue_kv(0, 0); CP_COMMIT();
    issue_kv(1, 1); CP_COMMIT();

    float o[16][4];
#pragma unroll
    for (int dt = 0; dt < 16; dt++)
#pragma unroll
        for (int k = 0; k < 4; k++) o[dt][k] = 0.0f;
    float m0 = -1e30f, m1 = -1e30f, l0 = 0.0f, l1 = 0.0f;

    uint32_t qrow = (uint32_t)((r0 + (lane & 15)) * 128 + ((lane >> 4) & 1) * 16);
    uint32_t krow = (uint32_t)((lane & 15) * 128 + ((lane >> 4) & 1) * 16);

    for (int t = 0; t < NTILES; t++) {
        CP_WAIT1();
        __syncthreads();
        uint32_t sK_ = sb + A_QBYTES + (uint32_t)(t & 1) * A_STG;
        uint32_t sV_ = sK_;

        // ---- S = Q K^T, 3 split terms, each fragment loaded once ----
        float sc[8][4];
#pragma unroll
        for (int nt = 0; nt < 8; nt++)
#pragma unroll
            for (int k = 0; k < 4; k++) sc[nt][k] = 0.0f;

#pragma unroll
        for (int ks = 0; ks < 8; ks++) {
            uint32_t co = (uint32_t)((ks & 3) * 32);
            uint32_t pq = (uint32_t)((ks >> 2) * 16384);
            uint32_t pk = (uint32_t)((ks >> 2) * 8192);
            uint32_t qoff = swz(qrow + co);
            uint32_t ah[4], al[4];
            LDMX4(ah[0], ah[1], ah[2], ah[3], sb + pq + qoff);
            LDMX4(al[0], al[1], al[2], al[3], sb + 32768u + pq + qoff);
            uint32_t bhx[4][4], blx[4][4];
#pragma unroll
            for (int g = 0; g < 4; g++) {
                uint32_t koff = swz(krow + g * 2048 + co);
                LDMX4(bhx[g][0], bhx[g][1], bhx[g][2], bhx[g][3], sK_ + pk + koff);
                LDMX4(blx[g][0], blx[g][1], blx[g][2], blx[g][3], sK_ + 16384u + pk + koff);
            }
#pragma unroll
            for (int nt = 0; nt < 8; nt++) {
                int g = nt >> 1, hb = nt & 1;
                MMA16816(sc[nt], ah, bhx[g][hb], bhx[g][hb + 2]);
                MMA16816(sc[nt], ah, blx[g][hb], blx[g][hb + 2]);
                MMA16816(sc[nt], al, bhx[g][hb], bhx[g][hb + 2]);
            }
        }

        // ---- mask (suffix tiles only) ----
        if (t >= 32) {
            int rg0 = r0 + (lane >> 2);
            int cb = t * 64 + (lane & 3) * 2;
#pragma unroll
            for (int nt = 0; nt < 8; nt++) {
                int c0 = cb + nt * 8;
                if (c0     > VLM + rg0)     sc[nt][0] = -1e30f;
                if (c0 + 1 > VLM + rg0)     sc[nt][1] = -1e30f;
                if (c0     > VLM + rg0 + 8) sc[nt][2] = -1e30f;
                if (c0 + 1 > VLM + rg0 + 8) sc[nt][3] = -1e30f;
            }
        }

        // ---- online softmax ----
        float rm0 = -1e30f, rm1 = -1e30f;
#pragma unroll
        for (int nt = 0; nt < 8; nt++) {
            rm0 = fmaxf(rm0, fmaxf(sc[nt][0], sc[nt][1]));
            rm1 = fmaxf(rm1, fmaxf(sc[nt][2], sc[nt][3]));
        }
        rm0 = fmaxf(rm0, __shfl_xor_sync(0xffffffffu, rm0, 1));
        rm0 = fmaxf(rm0, __shfl_xor_sync(0xffffffffu, rm0, 2));
        rm1 = fmaxf(rm1, __shfl_xor_sync(0xffffffffu, rm1, 1));
        rm1 = fmaxf(rm1, __shfl_xor_sync(0xffffffffu, rm1, 2));
        float mn0 = fmaxf(m0, rm0), mn1 = fmaxf(m1, rm1);
        float al0 = __expf(m0 - mn0), al1 = __expf(m1 - mn1);
        m0 = mn0; m1 = mn1;

        float rs0 = 0.0f, rs1 = 0.0f;
        uint32_t phi[4][4], plo[4][4];
#pragma unroll
        for (int nt = 0; nt < 8; nt++) {
            float p0f = __expf(sc[nt][0] - mn0);
            float p1f = __expf(sc[nt][1] - mn0);
            float p2f = __expf(sc[nt][2] - mn1);
            float p3f = __expf(sc[nt][3] - mn1);
            rs0 += p0f + p1f;
            rs1 += p2f + p3f;
            float h0 = __bfloat162float(__float2bfloat16(p0f));
            float h1 = __bfloat162float(__float2bfloat16(p1f));
            float h2 = __bfloat162float(__float2bfloat16(p2f));
            float h3 = __bfloat162float(__float2bfloat16(p3f));
            int kk = nt >> 1;
            int off = (nt & 1) * 2;
            phi[kk][off]     = pack_bf2(h0, h1);
            phi[kk][off + 1] = pack_bf2(h2, h3);
            plo[kk][off]     = pack_bf2(p0f - h0, p1f - h1);
            plo[kk][off + 1] = pack_bf2(p2f - h2, p3f - h3);
        }
        rs0 += __shfl_xor_sync(0xffffffffu, rs0, 1);
        rs0 += __shfl_xor_sync(0xffffffffu, rs0, 2);
        rs1 += __shfl_xor_sync(0xffffffffu, rs1, 1);
        rs1 += __shfl_xor_sync(0xffffffffu, rs1, 2);
        l0 = l0 * al0 + rs0;
        l1 = l1 * al1 + rs1;
#pragma unroll
        for (int dt = 0; dt < 16; dt++) {
            o[dt][0] *= al0; o[dt][1] *= al0;
            o[dt][2] *= al1; o[dt][3] *= al1;
        }

        // ---- O += P V  (3 split terms) ----
#pragma unroll
        for (int kk = 0; kk < 4; kk++) {
            uint32_t co = (uint32_t)(kk * 32);
#pragma unroll
            for (int g = 0; g < 8; g++) {
                uint32_t bhx[4], blx[4];
                uint32_t roff = swz(krow + g * 2048 + co);
                LDMX4(bhx[0], bhx[1], bhx[2], bhx[3], sV_ + 32768 + roff);
                LDMX4(blx[0], blx[1], blx[2], blx[3], sV_ + 49152 + roff);
                MMA16816(o[2*g],   phi[kk], bhx[0], bhx[2]);
                MMA16816(o[2*g],   phi[kk], blx[0], blx[2]);
                MMA16816(o[2*g],   plo[kk], bhx[0], bhx[2]);
                MMA16816(o[2*g+1], phi[kk], bhx[1], bhx[3]);
                MMA16816(o[2*g+1], phi[kk], blx[1], blx[3]);
                MMA16816(o[2*g+1], plo[kk], bhx[1], bhx[3]);
            }
        }
        __syncthreads();
        if (t + 2 < NTILES) issue_kv(t + 2, t & 1);
        CP_COMMIT();
    }

    // ---- epilogue: write split a2 (A-flavor [hi,hi,lo]) directly ----
    float i0 = 1.0f / l0, i1 = 1.0f / l1;
    int q0 = r0 + (lane >> 2);
    int cb = (lane & 3) * 2;
#pragma unroll
    for (int dt = 0; dt < 16; dt++) {
        int k = h * DD + cb + dt * 8;
        float v0 = o[dt][0] * i0, v1 = o[dt][1] * i0;
        float v2 = o[dt][2] * i1, v3 = o[dt][3] * i1;
        __nv_bfloat16 h0 = __float2bfloat16(v0), h1 = __float2bfloat16(v1);
        __nv_bfloat16 h2 = __float2bfloat16(v2), h3 = __float2bfloat16(v3);
        uint32_t hp0 = pack_bf2(__bfloat162float(h0), __bfloat162float(h1));
        uint32_t hp1 = pack_bf2(__bfloat162float(h2), __bfloat162float(h3));
        uint32_t lp0 = pack_bf2(v0 - __bfloat162float(h0), v1 - __bfloat162float(h1));
        uint32_t lp1 = pack_bf2(v2 - __bfloat162float(h2), v3 - __bfloat162float(h3));
        __nv_bfloat16* r0p = g_a2 + ((size_t)b * QL + q0) * KP;
        __nv_bfloat16* r1p = g_a2 + ((size_t)b * QL + q0 + 8) * KP;
        *(uint32_t*)(r0p + k)        = hp0;
        *(uint32_t*)(r0p + 2048 + k) = hp0;
        *(uint32_t*)(r0p + 4096 + k) = lp0;
        *(uint32_t*)(r1p + k)        = hp1;
        *(uint32_t*)(r1p + 2048 + k) = hp1;
        *(uint32_t*)(r1p + 4096 + k) = lp1;
    }
}

// ---------------- launch ----------------
extern "C" void kernel_launch(void* const* d_in, const int* in_sizes, int n_in,
                              void* d_out, int out_size) {
    const float* hidden = (const float*)d_in[0];
    const float* vlm_k  = (const float*)d_in[1];
    const float* vlm_v  = (const float*)d_in[2];
    const int*   pos    = (const int*)d_in[3];
    // d_in[4] attention_mask: reproduced analytically (prefix-visible + causal suffix)
    const float* wqkv   = (const float*)d_in[5];
    const float* wo     = (const float*)d_in[6];
    float* out = (float*)d_out;

    __nv_bfloat16 *h2_p, *w1_p, *w2_p, *a2_p;
    cudaGetSymbolAddress((void**)&h2_p, g_h2);
    cudaGetSymbolAddress((void**)&w1_p, g_w1);
    cudaGetSymbolAddress((void**)&w2_p, g_w2);
    cudaGetSymbolAddress((void**)&a2_p, g_a2);

    rope_table_kernel<<<(KVL * 64 + 255) / 256, 256>>>();

    prep_k_kernel<<<(128 * 2048 * 16) / 256, 256>>>(vlm_k);

    conv_split_kernel<<<(2048 * 2048 / 8) / 256, 256>>>(hidden, h2_p, 2048 * 2048 / 8, 0);
    conv_split_kernel<<<(4096 * 2048 / 8) / 256, 256>>>(wqkv,   w1_p, 4096 * 2048 / 8, 1);
    conv_split_kernel<<<(2048 * 2048 / 8) / 256, 256>>>(wo,     w2_p, 2048 * 2048 / 8, 1);

    cudaFuncSetAttribute(gemm_mma_kernel, cudaFuncAttributeMaxDynamicSharedMemorySize, GSMEM);

    // QKV projection + fused RoPE/split epilogue (mode 1): 256x128 tiles
    gemm_mma_kernel<<<dim3(NQKV / 128, (BB * QL) / 256), 512, GSMEM>>>(
        h2_p, w1_p, nullptr, NQKV, 1, pos);

    prep_vt_kernel<<<dim3(128, NTILES), 256>>>(vlm_v);

    cudaFuncSetAttribute(attn_mma_kernel, cudaFuncAttributeMaxDynamicSharedMemorySize, A_SMEM);
    attn_mma_kernel<<<BB * HH, 256, A_SMEM>>>();

    // output projection (mode 0, plain store to d_out): 256x128 tiles
    gemm_mma_kernel<<<dim3(HID / 128, (BB * QL) / 256), 512, GSMEM>>>(
        a2_p, w2_p, out, HID, 0, nullptr);
}